// round 4
// baseline (speedup 1.0000x reference)
#include <cuda_runtime.h>
#include <cuda_bf16.h>
#include <cstdint>

#define NN_MAX 100000
#define EE_MAX 1600000

// ---------------- device scratch (no allocs allowed) ----------------
__device__ __align__(16) int   g_deg[NN_MAX];
__device__ __align__(16) int   g_cursor[NN_MAX];
__device__ __align__(16) float g_dinv[NN_MAX];
__device__ __align__(16) int   g_off[NN_MAX + 1];
__device__ __align__(16) int   g_offpart[NN_MAX];
__device__ __align__(16) int   g_bsums[128];
__device__ __align__(16) int   g_bsums2[128];
__device__ __align__(16) int   g_srcs[EE_MAX];
__device__ __align__(16) float g_w[EE_MAX];
__device__ __align__(16) float g_h[(size_t)NN_MAX * 128];
__device__ __align__(16) float g_agg[(size_t)NN_MAX * 128];
__device__ int g_is64;

// ---------------- packed f32x2 helpers (FFMA2: 2x FFMA throughput) ---------
__device__ __forceinline__ void fma2(unsigned long long& d,
                                     unsigned long long a,
                                     unsigned long long b) {
    asm("fma.rn.f32x2 %0, %1, %2, %0;" : "+l"(d) : "l"(a), "l"(b));
}
__device__ __forceinline__ unsigned long long pack2(float lo, float hi) {
    unsigned long long r;
    asm("mov.b64 %0, {%1, %2};" : "=l"(r) : "f"(lo), "f"(hi));
    return r;
}
__device__ __forceinline__ float2 unpack2(unsigned long long v) {
    float lo, hi;
    asm("mov.b64 {%0, %1}, %2;" : "=f"(lo), "=f"(hi) : "l"(v));
    return make_float2(lo, hi);
}

// ---------------- buffer selectors -------------
__device__ __forceinline__ const float* sel_in(const float* ext, int sel) {
    return sel == 0 ? ext : (sel == 1 ? (const float*)g_h : (const float*)g_agg);
}
__device__ __forceinline__ float* sel_out(int sel) {
    return sel == 1 ? g_h : g_agg;
}

// ---------------- edge dtype detection (int64 vs int32) ----------------
__global__ void k_detect(const int* __restrict__ ei32) {
    if (threadIdx.x == 0 && blockIdx.x == 0) {
        int is64 = 1;
        #pragma unroll
        for (int k = 1; k < 64; k += 2)
            if (ei32[k] != 0) { is64 = 0; break; }
        g_is64 = is64;
    }
}

__device__ __forceinline__ int edge_at(const void* __restrict__ ei, long long i) {
    if (g_is64) return (int)((const long long*)ei)[i];
    return ((const int*)ei)[i];
}

// ---------------- degree / normalization ----------------
__global__ void k_init(int n) {
    int i = blockIdx.x * blockDim.x + threadIdx.x;
    if (i < n) { g_deg[i] = 1; g_cursor[i] = 0; }   // self-loop counts 1
}

__global__ void k_count(const void* __restrict__ ei, int E, int n) {
    int e = blockIdx.x * blockDim.x + threadIdx.x;
    if (e >= E) return;
    int d = edge_at(ei, (long long)E + e);
    if ((unsigned)d < (unsigned)n) atomicAdd(&g_deg[d], 1);
}

// ---------------- exclusive scan of edge counts (deg-1) ----------------
__global__ void k_scan1(int n) {
    __shared__ int sh[1024];
    int t = threadIdx.x;
    int i = blockIdx.x * 1024 + t;
    int c = (i < n) ? (g_deg[i] - 1) : 0;
    sh[t] = c;
    __syncthreads();
    for (int ofs = 1; ofs < 1024; ofs <<= 1) {
        int v = (t >= ofs) ? sh[t - ofs] : 0;
        __syncthreads();
        sh[t] += v;
        __syncthreads();
    }
    if (i < n) g_offpart[i] = sh[t] - c;
    if (t == 1023) g_bsums[blockIdx.x] = sh[1023];
}

__global__ void k_scan2(int nb) {
    __shared__ int sh[128];
    int t = threadIdx.x;
    int c = (t < nb) ? g_bsums[t] : 0;
    sh[t] = c;
    __syncthreads();
    for (int ofs = 1; ofs < 128; ofs <<= 1) {
        int v = (t >= ofs) ? sh[t - ofs] : 0;
        __syncthreads();
        sh[t] += v;
        __syncthreads();
    }
    g_bsums2[t] = sh[t] - c;
}

__global__ void k_scan3(int n, int E) {
    int i = blockIdx.x * blockDim.x + threadIdx.x;
    if (i < n) {
        g_off[i] = g_offpart[i] + g_bsums2[i >> 10];
        g_dinv[i] = rsqrtf((float)g_deg[i]);
    }
    if (i == 0) g_off[n] = E;
}

// ---------------- counting-sort edges by destination ----------------
__global__ void k_sort(const void* __restrict__ ei, int E, int n) {
    int e = blockIdx.x * blockDim.x + threadIdx.x;
    if (e >= E) return;
    int s = edge_at(ei, e);
    int d = edge_at(ei, (long long)E + e);
    if ((unsigned)s >= (unsigned)n || (unsigned)d >= (unsigned)n) return;
    int pos = g_off[d] + atomicAdd(&g_cursor[d], 1);
    if ((unsigned)pos < (unsigned)EE_MAX) {
        g_srcs[pos] = s;
        g_w[pos] = g_dinv[s] * g_dinv[d];
    }
}

// ---------------- SGEMM: C[M,128] = A[M,128] @ B[128,128] ----------------
__global__ void __launch_bounds__(256, 2)
k_gemm128(const float* __restrict__ Aext, int asel, int csel,
          const float* __restrict__ B, int M) {
    __shared__ __align__(16) float As[16][132];
    __shared__ __align__(16) float Bs[16][128];

    const float* A = sel_in(Aext, asel);
    float* C = sel_out(csel);

    int tid = threadIdx.x;
    int tx = tid & 15;
    int ty = tid >> 4;
    int rowBase = blockIdx.x * 128;

    int aR[2], aK[2], bK[2], bC[2];
    #pragma unroll
    for (int l = 0; l < 2; l++) {
        int idx = tid + l * 256;
        aR[l] = idx >> 2;
        aK[l] = (idx & 3) * 4;
        bK[l] = idx >> 5;
        bC[l] = (idx & 31) * 4;
    }

    unsigned long long acc[8][4];
    #pragma unroll
    for (int i = 0; i < 8; i++)
        #pragma unroll
        for (int j = 0; j < 4; j++) acc[i][j] = 0ull;

    float4 ra[2], rb[2];
    #pragma unroll
    for (int l = 0; l < 2; l++) {
        int gr = rowBase + aR[l];
        ra[l] = (gr < M)
            ? *reinterpret_cast<const float4*>(&A[(size_t)gr * 128 + aK[l]])
            : make_float4(0.f, 0.f, 0.f, 0.f);
        rb[l] = *reinterpret_cast<const float4*>(&B[(size_t)bK[l] * 128 + bC[l]]);
    }

    for (int k0 = 0; k0 < 128; k0 += 16) {
        #pragma unroll
        for (int l = 0; l < 2; l++) {
            As[aK[l] + 0][aR[l]] = ra[l].x;
            As[aK[l] + 1][aR[l]] = ra[l].y;
            As[aK[l] + 2][aR[l]] = ra[l].z;
            As[aK[l] + 3][aR[l]] = ra[l].w;
            *reinterpret_cast<float4*>(&Bs[bK[l]][bC[l]]) = rb[l];
        }
        __syncthreads();

        if (k0 < 112) {
            int kn = k0 + 16;
            #pragma unroll
            for (int l = 0; l < 2; l++) {
                int gr = rowBase + aR[l];
                ra[l] = (gr < M)
                    ? *reinterpret_cast<const float4*>(&A[(size_t)gr * 128 + kn + aK[l]])
                    : make_float4(0.f, 0.f, 0.f, 0.f);
                rb[l] = *reinterpret_cast<const float4*>(&B[(size_t)(kn + bK[l]) * 128 + bC[l]]);
            }
        }

        #pragma unroll
        for (int kk = 0; kk < 16; kk++) {
            float4 a0 = *reinterpret_cast<float4*>(&As[kk][ty * 8]);
            float4 a1 = *reinterpret_cast<float4*>(&As[kk][ty * 8 + 4]);
            float4 b0 = *reinterpret_cast<float4*>(&Bs[kk][tx * 8]);
            float4 b1 = *reinterpret_cast<float4*>(&Bs[kk][tx * 8 + 4]);
            unsigned long long bb[4];
            bb[0] = pack2(b0.x, b0.y);
            bb[1] = pack2(b0.z, b0.w);
            bb[2] = pack2(b1.x, b1.y);
            bb[3] = pack2(b1.z, b1.w);
            float av[8] = {a0.x, a0.y, a0.z, a0.w, a1.x, a1.y, a1.z, a1.w};
            #pragma unroll
            for (int i = 0; i < 8; i++) {
                unsigned long long aa = pack2(av[i], av[i]);
                fma2(acc[i][0], aa, bb[0]);
                fma2(acc[i][1], aa, bb[1]);
                fma2(acc[i][2], aa, bb[2]);
                fma2(acc[i][3], aa, bb[3]);
            }
        }
        __syncthreads();
    }

    #pragma unroll
    for (int i = 0; i < 8; i++) {
        int gr = rowBase + ty * 8 + i;
        if (gr < M) {
            float2 v0 = unpack2(acc[i][0]);
            float2 v1 = unpack2(acc[i][1]);
            float2 v2 = unpack2(acc[i][2]);
            float2 v3 = unpack2(acc[i][3]);
            float4 o0 = make_float4(v0.x, v0.y, v1.x, v1.y);
            float4 o1 = make_float4(v2.x, v2.y, v3.x, v3.y);
            *reinterpret_cast<float4*>(&C[(size_t)gr * 128 + tx * 8]) = o0;
            *reinterpret_cast<float4*>(&C[(size_t)gr * 128 + tx * 8 + 4]) = o1;
        }
    }
}

// ---------------- aggregation F=128 (layer 1): plain -----------------------
__global__ void k_agg128(const float* __restrict__ bias, int hsel, int osel, int n) {
    int node = (blockIdx.x * blockDim.x + threadIdx.x) >> 5;
    int lane = threadIdx.x & 31;
    if (node >= n) return;

    const float4* h4 = reinterpret_cast<const float4*>(sel_in(nullptr, hsel));
    float4* o4 = reinterpret_cast<float4*>(sel_out(osel));

    float dv = g_dinv[node];
    float sw = dv * dv;
    float4 acc = h4[(size_t)node * 32 + lane];
    acc.x *= sw; acc.y *= sw; acc.z *= sw; acc.w *= sw;

    int e0 = g_off[node];
    int e1 = g_off[node + 1];
    for (int e = e0; e < e1; e++) {
        int s = g_srcs[e];
        float we = g_w[e];
        float4 v = h4[(size_t)s * 32 + lane];
        acc.x = fmaf(v.x, we, acc.x);
        acc.y = fmaf(v.y, we, acc.y);
        acc.z = fmaf(v.z, we, acc.z);
        acc.w = fmaf(v.w, we, acc.w);
    }
    float4 b = reinterpret_cast<const float4*>(bias)[lane];
    acc.x = fmaxf(acc.x + b.x, 0.f);
    acc.y = fmaxf(acc.y + b.y, 0.f);
    acc.z = fmaxf(acc.z + b.z, 0.f);
    acc.w = fmaxf(acc.w + b.w, 0.f);
    o4[(size_t)node * 32 + lane] = acc;
}

// ------- aggregation F=128 (layer 2) fused with 128->8 projection ----------
// g_agg[node,0:8] = relu(agg2(g_h) + b2) @ W3   (h2 never materialized)
__global__ void k_agg128_proj(const float* __restrict__ bias,
                              const float* __restrict__ W3, int n) {
    __shared__ float Ws[128 * 8];
    for (int i = threadIdx.x; i < 1024; i += blockDim.x) Ws[i] = W3[i];
    __syncthreads();

    int node = (blockIdx.x * blockDim.x + threadIdx.x) >> 5;
    int lane = threadIdx.x & 31;
    if (node >= n) return;

    const float4* h4 = reinterpret_cast<const float4*>((const float*)g_h);

    float dv = g_dinv[node];
    float sw = dv * dv;
    float4 acc = h4[(size_t)node * 32 + lane];
    acc.x *= sw; acc.y *= sw; acc.z *= sw; acc.w *= sw;

    int e0 = g_off[node];
    int e1 = g_off[node + 1];
    for (int e = e0; e < e1; e++) {
        int s = g_srcs[e];
        float we = g_w[e];
        float4 v = h4[(size_t)s * 32 + lane];
        acc.x = fmaf(v.x, we, acc.x);
        acc.y = fmaf(v.y, we, acc.y);
        acc.z = fmaf(v.z, we, acc.z);
        acc.w = fmaf(v.w, we, acc.w);
    }
    float4 b = reinterpret_cast<const float4*>(bias)[lane];
    acc.x = fmaxf(acc.x + b.x, 0.f);
    acc.y = fmaxf(acc.y + b.y, 0.f);
    acc.z = fmaxf(acc.z + b.z, 0.f);
    acc.w = fmaxf(acc.w + b.w, 0.f);

    // project: y[j] = sum_k h2[k] * W3[k][j], k = 4*lane + c
    int kb = lane * 4;
    float y[8];
    #pragma unroll
    for (int j = 0; j < 8; j++) {
        float p = acc.x * Ws[(kb + 0) * 8 + j];
        p = fmaf(acc.y, Ws[(kb + 1) * 8 + j], p);
        p = fmaf(acc.z, Ws[(kb + 2) * 8 + j], p);
        p = fmaf(acc.w, Ws[(kb + 3) * 8 + j], p);
        y[j] = p;
    }
    #pragma unroll
    for (int j = 0; j < 8; j++) {
        #pragma unroll
        for (int ofs = 16; ofs > 0; ofs >>= 1)
            y[j] += __shfl_xor_sync(0xffffffffu, y[j], ofs);
    }
    if (lane < 8) g_agg[(size_t)node * 8 + lane] = y[lane];
}

// ------- aggregation F=8 fused with classifier (8->16) ---------------------
// h3 = relu(agg(g_agg 8-wide) + b3); out[node,0:16] = h3 @ Wc + bc
__global__ void k_agg8cls(const float* __restrict__ b3,
                          const float* __restrict__ Wc,
                          const float* __restrict__ bc,
                          float* __restrict__ out, int n) {
    __shared__ float Ws[8 * 16];
    __shared__ float bs[16];
    if (threadIdx.x < 128) Ws[threadIdx.x] = Wc[threadIdx.x];
    if (threadIdx.x < 16) bs[threadIdx.x] = bc[threadIdx.x];
    __syncthreads();

    int t = blockIdx.x * blockDim.x + threadIdx.x;
    int node = t >> 3;
    int f = t & 7;
    if (node >= n) return;

    float dv = g_dinv[node];
    float acc = g_agg[(size_t)node * 8 + f] * dv * dv;
    int e0 = g_off[node];
    int e1 = g_off[node + 1];
    for (int e = e0; e < e1; e++) {
        int s = g_srcs[e];
        acc = fmaf(g_agg[(size_t)s * 8 + f], g_w[e], acc);
    }
    float h3 = fmaxf(acc + b3[f], 0.f);

    // exchange h3 across the 8-lane group, compute 2 output cols per thread
    unsigned mask = 0xffffffffu;
    int base = (threadIdx.x & 31) & ~7;      // group base lane
    float o0 = bs[f], o1 = bs[f + 8];
    #pragma unroll
    for (int fp = 0; fp < 8; fp++) {
        float hv = __shfl_sync(mask, h3, base + fp);
        o0 = fmaf(hv, Ws[fp * 16 + f], o0);
        o1 = fmaf(hv, Ws[fp * 16 + f + 8], o1);
    }
    out[(size_t)node * 16 + f] = o0;
    out[(size_t)node * 16 + f + 8] = o1;
}

// ---------------- launch ----------------
extern "C" void kernel_launch(void* const* d_in, const int* in_sizes, int n_in,
                              void* d_out, int out_size) {
    const float* x  = (const float*)d_in[0];
    const void*  ei = d_in[1];
    const float* W1 = (const float*)d_in[2];
    const float* b1 = (const float*)d_in[3];
    const float* W2 = (const float*)d_in[4];
    const float* b2 = (const float*)d_in[5];
    const float* W3 = (const float*)d_in[6];
    const float* b3 = (const float*)d_in[7];
    const float* Wc = (const float*)d_in[8];
    const float* bc = (const float*)d_in[9];
    float* out = (float*)d_out;

    int n = in_sizes[0] / 128;
    int E = in_sizes[1] / 2;

    int gemmGrid = (n + 127) / 128;
    int aggGrid128 = (int)(((long long)n * 32 + 255) / 256);
    int nb = (n + 1023) / 1024;

    // fork: graph prep on side stream, GEMM1 on main stream (independent)
    cudaStream_t s2;
    bool forked = (cudaStreamCreateWithFlags(&s2, cudaStreamNonBlocking) == cudaSuccess);
    cudaEvent_t eFork = nullptr, eJoin = nullptr;
    if (forked) {
        forked = (cudaEventCreateWithFlags(&eFork, cudaEventDisableTiming) == cudaSuccess) &&
                 (cudaEventCreateWithFlags(&eJoin, cudaEventDisableTiming) == cudaSuccess);
    }

    if (forked) {
        cudaEventRecord(eFork, 0);
        cudaStreamWaitEvent(s2, eFork, 0);
        k_detect<<<1, 32, 0, s2>>>((const int*)ei);
        k_init<<<(n + 255) / 256, 256, 0, s2>>>(n);
        k_count<<<(E + 255) / 256, 256, 0, s2>>>(ei, E, n);
        k_scan1<<<nb, 1024, 0, s2>>>(n);
        k_scan2<<<1, 128, 0, s2>>>(nb);
        k_scan3<<<(n + 255) / 256, 256, 0, s2>>>(n, E);
        k_sort<<<(E + 255) / 256, 256, 0, s2>>>(ei, E, n);
        cudaEventRecord(eJoin, s2);
        // concurrent: layer-1 GEMM on the main (capture) stream
        k_gemm128<<<gemmGrid, 256>>>(x, 0, 1, W1, n);
        cudaStreamWaitEvent(0, eJoin, 0);
    } else {
        k_detect<<<1, 32>>>((const int*)ei);
        k_init<<<(n + 255) / 256, 256>>>(n);
        k_count<<<(E + 255) / 256, 256>>>(ei, E, n);
        k_scan1<<<nb, 1024>>>(n);
        k_scan2<<<1, 128>>>(nb);
        k_scan3<<<(n + 255) / 256, 256>>>(n, E);
        k_sort<<<(E + 255) / 256, 256>>>(ei, E, n);
        k_gemm128<<<gemmGrid, 256>>>(x, 0, 1, W1, n);
    }

    // layer 1 agg: g_h -> g_agg (128w)
    k_agg128<<<aggGrid128, 256>>>(b1, 1, 2, n);
    // layer 2 gemm: g_agg -> g_h (128w)
    k_gemm128<<<gemmGrid, 256>>>(nullptr, 2, 1, W2, n);
    // layer 2 agg + relu + b2 + @W3: g_h -> g_agg (8w)
    k_agg128_proj<<<aggGrid128, 256>>>(b2, W3, n);
    // layer 3 agg + b3 + relu + classifier: g_agg -> out
    k_agg8cls<<<(int)(((long long)n * 8 + 255) / 256), 256>>>(b3, Wc, bc, out, n);

    if (eFork) cudaEventDestroy(eFork);
    if (eJoin) cudaEventDestroy(eJoin);
    if (forked) cudaStreamDestroy(s2);
}